// round 16
// baseline (speedup 1.0000x reference)
#include <cuda_runtime.h>
#include <cuda_bf16.h>
#include <math.h>
#include <stdint.h>

#define Bq 128
#define Sq 4096
#define Hq 512
#define Vq 32000
#define NCHUNK 32           // 32 chunks of 128 s each

// ---------------- scratch (no allocations allowed) ----------------
__device__ float g_hnew[Bq * Hq];
__device__ float g_scores[Bq * Sq];
__device__ float g_pm[Bq * NCHUNK];
__device__ float g_pz[Bq * NCHUNK];
__device__ float g_pctx[Bq * NCHUNK * Hq];
__device__ float g_concat_in[Bq * 2 * Hq];
__device__ float g_concat_out[Bq * Hq];
__device__ float g_gemm_part [8 * Bq * 3 * Hq];
__device__ float g_gemm_part2[8 * Bq * 3 * Hq];
__device__ int   g_cnt1 = 0, g_fin1 = 0;   // gemm_gru grid barrier
__device__ int   g_cnt2 = 0, g_fin2 = 0;   // concat gemm grid barrier

// ---------------- grid barrier helpers (all blocks co-resident) ----------------
__device__ __forceinline__ void grid_arrive_wait(int* cnt, int nblocks)
{
    __syncthreads();
    __threadfence();
    if (threadIdx.x == 0) {
        atomicAdd(cnt, 1);
        while (*((volatile int*)cnt) < nblocks) __nanosleep(64);
    }
    __syncthreads();
    __threadfence();
}
__device__ __forceinline__ void grid_finish_reset(int* cnt, int* fin, int nblocks)
{
    __syncthreads();
    if (threadIdx.x == 0) {
        int d = atomicAdd(fin, 1);
        if (d == nblocks - 1) { *cnt = 0; *fin = 0; }
    }
}

// ---------------- tf32 helpers ----------------
__device__ __forceinline__ uint32_t f2tf32(float x) {
    uint32_t r;
    asm("cvt.rna.tf32.f32 %0, %1;" : "=r"(r) : "f"(x));
    return r;
}
__device__ __forceinline__ float tf32f(float x) { return __uint_as_float(f2tf32(x)); }
__device__ __forceinline__ void mma_tf32(float* d, const uint32_t* a, const uint32_t* b) {
    asm("mma.sync.aligned.m16n8k8.row.col.f32.tf32.tf32.f32 "
        "{%0,%1,%2,%3}, {%4,%5,%6,%7}, {%8,%9}, {%0,%1,%2,%3};"
        : "+f"(d[0]), "+f"(d[1]), "+f"(d[2]), "+f"(d[3])
        : "r"(a[0]), "r"(a[1]), "r"(a[2]), "r"(a[3]), "r"(b[0]), "r"(b[1]));
}
__device__ __forceinline__ void cp16(void* dst_smem, const void* src) {
    uint32_t d = (uint32_t)__cvta_generic_to_shared(dst_smem);
    asm volatile("cp.async.ca.shared.global [%0], [%1], 16;" :: "r"(d), "l"(src));
}
__device__ __forceinline__ void cp_commit() { asm volatile("cp.async.commit_group;"); }
template<int N> __device__ __forceinline__ void cp_wait() {
    asm volatile("cp.async.wait_group %0;" :: "n"(N));
}

#define LDA 20
#define TILE_F (128 * LDA)
#define GEMM_SMEM_BYTES (3 * 2 * TILE_F * 4)

// vocab: k32 stages, padded stride 36 -> (36r+c)%32 = 4r+c, conflict-free
#define VLDA 36
#define VTILE_F (128 * VLDA)
#define VOC_SMEM_BYTES (3 * 2 * VTILE_F * 4)   // 110592 B -> 2 CTAs/SM

// ---------------- generic tf32x3 body (gru/concat), 3-deep cp.async ring ----------------
__device__ __forceinline__
void gemm_body(const float* aptr0, const float* aptr1,
               const float* wptr0, const float* wptr1,
               float* __restrict__ part, int N,
               int nblk, int nsteps)
{
    extern __shared__ float smx[];
    float* Asm = smx;
    float* Wsm = smx + 3 * TILE_F;

    int t = threadIdx.x;
    int wid = t >> 5, lane = t & 31;
    int lr = lane >> 2, lc = lane & 3;
    int m0 = (wid & 3) * 32;
    int n0 = (wid >> 2) * 64;
    int r0 = t >> 2;
    int k4 = (t & 3) * 4;

    float acc[2][8][4];
#pragma unroll
    for (int i = 0; i < 2; i++)
#pragma unroll
        for (int j = 0; j < 8; j++)
#pragma unroll
            for (int c = 0; c < 4; c++) acc[i][j][c] = 0.f;

#define STAGE(buf, step)                                              \
    do {                                                              \
        float* Ad = Asm + (buf) * TILE_F;                             \
        float* Wd = Wsm + (buf) * TILE_F;                             \
        cp16(Ad + r0 * LDA + k4,        aptr0 + (step) * 16);         \
        cp16(Ad + (r0 + 64) * LDA + k4, aptr1 + (step) * 16);         \
        cp16(Wd + r0 * LDA + k4,        wptr0 + (step) * 16);         \
        cp16(Wd + (r0 + 64) * LDA + k4, wptr1 + (step) * 16);         \
        cp_commit();                                                  \
    } while (0)

#pragma unroll
    for (int p = 0; p < 3; p++) {
        if (p < nsteps) STAGE(p, p);
        else cp_commit();
    }

    for (int i = 0; i < nsteps; i++) {
        cp_wait<2>();
        __syncthreads();
        int buf = i % 3;
        const float* Ab = Asm + buf * TILE_F;
        const float* Wb = Wsm + buf * TILE_F;
#pragma unroll
        for (int ks = 0; ks < 2; ks++) {
            int k0 = ks * 8;
            uint32_t ah[2][4], al[2][4];
#pragma unroll
            for (int tt = 0; tt < 2; tt++) {
                int rb = m0 + tt * 16;
#pragma unroll
                for (int q = 0; q < 4; q++) {
                    int rr = rb + lr + (q & 1) * 8;
                    int cc = k0 + lc + (q >> 1) * 4;
                    float x = Ab[rr * LDA + cc];
                    uint32_t hi = f2tf32(x);
                    ah[tt][q] = hi;
                    al[tt][q] = f2tf32(x - __uint_as_float(hi));
                }
            }
#pragma unroll
            for (int j = 0; j < 8; j++) {
                int rn = (n0 + j * 8 + lr) * LDA;
                float x0 = Wb[rn + k0 + lc];
                float x1 = Wb[rn + k0 + lc + 4];
                uint32_t bh[2], bl[2];
                bh[0] = f2tf32(x0); bl[0] = f2tf32(x0 - __uint_as_float(bh[0]));
                bh[1] = f2tf32(x1); bl[1] = f2tf32(x1 - __uint_as_float(bh[1]));
#pragma unroll
                for (int tt = 0; tt < 2; tt++) {
                    mma_tf32(acc[tt][j], ah[tt], bh);
                    mma_tf32(acc[tt][j], ah[tt], bl);
                    mma_tf32(acc[tt][j], al[tt], bh);
                }
            }
        }
        __syncthreads();
        int nx = i + 3;
        if (nx < nsteps) STAGE(buf, nx);
        else cp_commit();
    }
#undef STAGE

#pragma unroll
    for (int tt = 0; tt < 2; tt++)
#pragma unroll
        for (int j = 0; j < 8; j++) {
            int gr = m0 + tt * 16 + lr;
            int gc = nblk + n0 + j * 8 + 2 * lc;
            *(float2*)(part + (size_t)gr * N + gc) = make_float2(acc[tt][j][0], acc[tt][j][1]);
            *(float2*)(part + (size_t)(gr + 8) * N + gc) = make_float2(acc[tt][j][2], acc[tt][j][3]);
        }
}

// ---------------- vocab GEMM v3: k32 stages, pre-rounded A, tf32 x1 ----------------
// C[128,Vq] = A[128,512] @ W[Vq,512]^T + bias. grid 250, block 256, 2 CTAs/SM.
__global__ __launch_bounds__(256, 2)
void gemm_vocab(const float* __restrict__ A,      // tf32-prerounded
                const float* __restrict__ W,
                const float* __restrict__ bias,
                float* __restrict__ C)
{
    extern __shared__ float smx[];
    float* Asm = smx;
    float* Wsm = smx + 3 * VTILE_F;

    const int K = Hq;
    const int N = Vq;
    int t = threadIdx.x;
    int wid = t >> 5, lane = t & 31;
    int lr = lane >> 2, lc = lane & 3;
    int m0 = (wid & 3) * 32;
    int n0 = (wid >> 2) * 64;
    int nblk = blockIdx.x * 128;
    int row = t >> 1;                // 0..127, 2 threads/row
    int kseg = (t & 1) * 16;         // halves of a 32-float k-chunk

    const float* aptr = A + (size_t)row * K + kseg;
    const float* wptr = W + (size_t)(nblk + row) * K + kseg;

    float acc[2][8][4];
#pragma unroll
    for (int i = 0; i < 2; i++)
#pragma unroll
        for (int j = 0; j < 8; j++)
#pragma unroll
            for (int c = 0; c < 4; c++) acc[i][j][c] = 0.f;

    const int nsteps = K / 32;       // 16

#define VSTG(buf, step)                                               \
    do {                                                              \
        float* Ad = Asm + (buf) * VTILE_F + row * VLDA + kseg;        \
        float* Wd = Wsm + (buf) * VTILE_F + row * VLDA + kseg;        \
        const float* as = aptr + (step) * 32;                         \
        const float* ws = wptr + (step) * 32;                         \
        cp16(Ad,      as);     cp16(Ad + 4,  as + 4);                 \
        cp16(Ad + 8,  as + 8); cp16(Ad + 12, as + 12);                \
        cp16(Wd,      ws);     cp16(Wd + 4,  ws + 4);                 \
        cp16(Wd + 8,  ws + 8); cp16(Wd + 12, ws + 12);                \
        cp_commit();                                                  \
    } while (0)

    VSTG(0, 0); VSTG(1, 1); VSTG(2, 2);

    for (int i = 0; i < nsteps; i++) {
        cp_wait<2>();
        __syncthreads();
        int buf = i % 3;
        const float* Ab = Asm + buf * VTILE_F;
        const float* Wb = Wsm + buf * VTILE_F;
#pragma unroll
        for (int ks = 0; ks < 4; ks++) {
            int k0 = ks * 8;
            uint32_t ah[2][4];
#pragma unroll
            for (int tt = 0; tt < 2; tt++) {
                int rb = m0 + tt * 16;
                ah[tt][0] = __float_as_uint(Ab[(rb + lr) * VLDA + k0 + lc]);
                ah[tt][1] = __float_as_uint(Ab[(rb + lr + 8) * VLDA + k0 + lc]);
                ah[tt][2] = __float_as_uint(Ab[(rb + lr) * VLDA + k0 + lc + 4]);
                ah[tt][3] = __float_as_uint(Ab[(rb + lr + 8) * VLDA + k0 + lc + 4]);
            }
#pragma unroll
            for (int j = 0; j < 8; j++) {
                int rn = (n0 + j * 8 + lr) * VLDA;
                uint32_t bh[2];
                bh[0] = f2tf32(Wb[rn + k0 + lc]);
                bh[1] = f2tf32(Wb[rn + k0 + lc + 4]);
                mma_tf32(acc[0][j], ah[0], bh);
                mma_tf32(acc[1][j], ah[1], bh);
            }
        }
        __syncthreads();
        int nx = i + 3;
        if (nx < nsteps) VSTG(buf, nx);
        else cp_commit();
    }
#undef VSTG

#pragma unroll
    for (int tt = 0; tt < 2; tt++)
#pragma unroll
        for (int j = 0; j < 8; j++) {
            int gr = m0 + tt * 16 + lr;
            int gc = nblk + n0 + j * 8 + 2 * lc;
            float b0 = bias[gc], b1 = bias[gc + 1];
            *(float2*)(C + (size_t)gr * N + gc) = make_float2(acc[tt][j][0] + b0, acc[tt][j][1] + b1);
            *(float2*)(C + (size_t)(gr + 8) * N + gc) = make_float2(acc[tt][j][2] + b0, acc[tt][j][3] + b1);
        }
}

// fused GRU GEMMs + embedding gather + grid-barrier + gate epilogue
#define GRU_NB 192
__global__ __launch_bounds__(256, 2)
void gemm_gru(const float* __restrict__ hprev,
              const float* __restrict__ W_ih, const float* __restrict__ W_hh,
              const int* __restrict__ seq, const int* __restrict__ pos,
              const int* __restrict__ yr, const int* __restrict__ fr,
              const float* __restrict__ et, const float* __restrict__ ep,
              const float* __restrict__ ey, const float* __restrict__ ei,
              const float* __restrict__ b_ih, const float* __restrict__ b_hh,
              float* __restrict__ out_h)
{
    int N = 3 * Hq;
    int nblk = blockIdx.x * 128;
    int t = threadIdx.x;
    int r0 = t >> 2;
    int k4 = (t & 3) * 4;
    if (blockIdx.z == 0) {
        int K = 4 * Hq;
        int klen = K / 8;               // 256 -> one table per split
        int kstart = blockIdx.y * klen;
        int region = blockIdx.y >> 1;
        int coff = (blockIdx.y & 1) * 256 + k4;
        const float* tbl; const int* idxa;
        if (region == 0)      { tbl = et; idxa = seq; }
        else if (region == 1) { tbl = ep; idxa = pos; }
        else if (region == 2) { tbl = ey; idxa = yr; }
        else                  { tbl = ei; idxa = fr; }
        const float* a0 = tbl + (size_t)idxa[r0] * Hq + coff;
        const float* a1 = tbl + (size_t)idxa[r0 + 64] * Hq + coff;
        gemm_body(a0, a1,
                  W_ih + (size_t)(nblk + r0) * K + kstart + k4,
                  W_ih + (size_t)(nblk + r0 + 64) * K + kstart + k4,
                  g_gemm_part + (size_t)blockIdx.y * 128 * N, N,
                  nblk, klen / 16);
    } else {
        int K = Hq;
        int klen = K / 8;
        int kstart = blockIdx.y * klen;
        gemm_body(hprev + (size_t)r0 * K + kstart + k4,
                  hprev + (size_t)(r0 + 64) * K + kstart + k4,
                  W_hh + (size_t)(nblk + r0) * K + kstart + k4,
                  W_hh + (size_t)(nblk + r0 + 64) * K + kstart + k4,
                  g_gemm_part2 + (size_t)blockIdx.y * 128 * N, N,
                  nblk, klen / 16);
    }

    grid_arrive_wait(&g_cnt1, GRU_NB);

    int lb = (blockIdx.z * 8 + blockIdx.y) * 12 + blockIdx.x;
    for (int idx = lb * 256 + t; idx < Bq * Hq; idx += GRU_NB * 256) {
        int b = idx >> 9;
        int j = idx & 511;
        float xr = 0.f, xz = 0.f, xn = 0.f, hr = 0.f, hz = 0.f, hn = 0.f;
#pragma unroll
        for (int z = 0; z < 8; z++) {
            const float* P0 = g_gemm_part  + ((size_t)z * Bq + b) * (3 * Hq);
            const float* P1 = g_gemm_part2 + ((size_t)z * Bq + b) * (3 * Hq);
            xr += P0[j]; xz += P0[Hq + j]; xn += P0[2 * Hq + j];
            hr += P1[j]; hz += P1[Hq + j]; hn += P1[2 * Hq + j];
        }
        xr += b_ih[j]; xz += b_ih[Hq + j]; xn += b_ih[2 * Hq + j];
        hr += b_hh[j]; hz += b_hh[Hq + j]; hn += b_hh[2 * Hq + j];
        float r = 1.f / (1.f + __expf(-(xr + hr)));
        float z = 1.f / (1.f + __expf(-(xz + hz)));
        float n = tanhf(xn + r * hn);
        float hnew = (1.f - z) * n + z * hprev[idx];
        g_hnew[idx] = hnew;
        g_concat_in[(size_t)b * 2 * Hq + j] = hnew;
        if (out_h) out_h[idx] = hnew;
    }

    grid_finish_reset(&g_cnt1, &g_fin1, GRU_NB);
}

// concat GEMM + grid-barrier + split-K reduce + tanh epilogue
// grid (4, 16) = 64 blocks (co-resident)
#define CC_NB 64
__global__ __launch_bounds__(256, 2)
void gemm_concat(const float* __restrict__ W_concat,
                 const float* __restrict__ b_concat)
{
    int N = Hq;
    int K = 2 * Hq;
    int klen = K / 16;                  // 64 -> nsteps 4
    int kstart = blockIdx.y * klen;
    int nblk = blockIdx.x * 128;
    int t = threadIdx.x;
    int r0 = t >> 2;
    int k4 = (t & 3) * 4;
    const float* A = g_concat_in;
    gemm_body(A + (size_t)r0 * K + kstart + k4,
              A + (size_t)(r0 + 64) * K + kstart + k4,
              W_concat + (size_t)(nblk + r0) * K + kstart + k4,
              W_concat + (size_t)(nblk + r0 + 64) * K + kstart + k4,
              g_gemm_part + (size_t)blockIdx.y * 128 * N, N,
              nblk, klen / 16);

    grid_arrive_wait(&g_cnt2, CC_NB);

    int lb = blockIdx.y * 4 + blockIdx.x;
    for (int idx = lb * 256 + t; idx < Bq * Hq; idx += CC_NB * 256) {
        float s = 0.f;
#pragma unroll
        for (int z = 0; z < 16; z++)
            s += g_gemm_part[(size_t)z * Bq * Hq + idx];
        s += b_concat[idx & 511];
        // pre-round to tf32: bit-identical to rounding at vocab fragment load
        g_concat_out[idx] = tf32f(tanhf(s));
    }

    grid_finish_reset(&g_cnt2, &g_fin2, CC_NB);
}

// ---------------- fused attention: single pass over enc ----------------
__global__ __launch_bounds__(128)
void attn_fused_kernel(const float* __restrict__ enc)
{
    int b = blockIdx.y;
    int t = threadIdx.x;
    int w = t >> 5;
    int lane = t & 31;
    int chunk = blockIdx.x * 4 + w;

    const float4* h4 = (const float4*)(g_hnew + (size_t)b * Hq);
    float4 h0 = h4[lane];
    float4 h1 = h4[lane + 32];
    float4 h2 = h4[lane + 64];
    float4 h3 = h4[lane + 96];

    float m = -1e30f, Z = 0.f;
    float4 c0 = make_float4(0.f,0.f,0.f,0.f), c1 = c0, c2 = c0, c3 = c0;

    int sbase = chunk * 128;
#pragma unroll 2
    for (int s0 = 0; s0 < 128; s0++) {
        int s = sbase + s0;
        const float4* e4 = (const float4*)(enc + ((size_t)s * Bq + b) * Hq);
        float4 e0 = e4[lane];
        float4 e1 = e4[lane + 32];
        float4 e2 = e4[lane + 64];
        float4 e3 = e4[lane + 96];
        float dp = e0.x*h0.x + e0.y*h0.y + e0.z*h0.z + e0.w*h0.w
                 + e1.x*h1.x + e1.y*h1.y + e1.z*h1.z + e1.w*h1.w
                 + e2.x*h2.x + e2.y*h2.y + e2.z*h2.z + e2.w*h2.w
                 + e3.x*h3.x + e3.y*h3.y + e3.z*h3.z + e3.w*h3.w;
#pragma unroll
        for (int off = 16; off > 0; off >>= 1)
            dp += __shfl_xor_sync(0xffffffffu, dp, off);
        if (lane == 0) g_scores[(size_t)b * Sq + s] = dp;
        if (dp <= m) {
            float p = __expf(dp - m);
            Z += p;
            c0.x += p*e0.x; c0.y += p*e0.y; c0.z += p*e0.z; c0.w += p*e0.w;
            c1.x += p*e1.x; c1.y += p*e1.y; c1.z += p*e1.z; c1.w += p*e1.w;
            c2.x += p*e2.x; c2.y += p*e2.y; c2.z += p*e2.z; c2.w += p*e2.w;
            c3.x += p*e3.x; c3.y += p*e3.y; c3.z += p*e3.z; c3.w += p*e3.w;
        } else {
            float corr = __expf(m - dp);
            Z = Z * corr + 1.f;
            c0.x = c0.x*corr + e0.x; c0.y = c0.y*corr + e0.y; c0.z = c0.z*corr + e0.z; c0.w = c0.w*corr + e0.w;
            c1.x = c1.x*corr + e1.x; c1.y = c1.y*corr + e1.y; c1.z = c1.z*corr + e1.z; c1.w = c1.w*corr + e1.w;
            c2.x = c2.x*corr + e2.x; c2.y = c2.y*corr + e2.y; c2.z = c2.z*corr + e2.z; c2.w = c2.w*corr + e2.w;
            c3.x = c3.x*corr + e3.x; c3.y = c3.y*corr + e3.y; c3.z = c3.z*corr + e3.z; c3.w = c3.w*corr + e3.w;
            m = dp;
        }
    }

    int pc = b * NCHUNK + chunk;
    float4* pctx = (float4*)(g_pctx + (size_t)pc * Hq);
    pctx[lane]      = c0;
    pctx[lane + 32] = c1;
    pctx[lane + 64] = c2;
    pctx[lane + 96] = c3;
    if (lane == 0) { g_pm[pc] = m; g_pz[pc] = Z; }
}

// ---------------- merged attention epilogue ----------------
__global__ __launch_bounds__(256)
void attn_epilogue_kernel(float* __restrict__ out_attn)
{
    __shared__ float s_scale[NCHUNK];
    __shared__ float s_M, s_Zinv;
    int b = blockIdx.y;
    int part = blockIdx.x;
    int t = threadIdx.x;

    if (t < 32) {
        float m = g_pm[b * NCHUNK + t];
        float z = g_pz[b * NCHUNK + t];
        float M = m;
#pragma unroll
        for (int off = 16; off > 0; off >>= 1)
            M = fmaxf(M, __shfl_xor_sync(0xffffffffu, M, off));
        float e = __expf(m - M);
        float zs = z * e;
#pragma unroll
        for (int off = 16; off > 0; off >>= 1)
            zs += __shfl_xor_sync(0xffffffffu, zs, off);
        float zinv = 1.f / zs;
        s_scale[t] = e * zinv;
        if (t == 0) { s_M = M; s_Zinv = zinv; }
    }
    __syncthreads();

    if (part < 2) {
        int h = part * 256 + t;
        const float* p = g_pctx + (size_t)b * NCHUNK * Hq + h;
        float a = 0.f;
#pragma unroll 8
        for (int c = 0; c < NCHUNK; c++)
            a += p[(size_t)c * Hq] * s_scale[c];
        g_concat_in[(size_t)b * 2 * Hq + Hq + h] = a;
    } else if (out_attn) {
        int s = (part - 2) * 256 + t;
        out_attn[(size_t)b * Sq + s] =
            __expf(g_scores[(size_t)b * Sq + s] - s_M) * s_Zinv;
    }
}

// ---------------- launch ----------------
extern "C" void kernel_launch(void* const* d_in, const int* in_sizes, int n_in,
                              void* d_out, int out_size)
{
    const int* input_seq   = (const int*)d_in[0];
    const int* positions   = (const int*)d_in[1];
    const int* years       = (const int*)d_in[2];
    const int* froms       = (const int*)d_in[3];
    const float* last_h    = (const float*)d_in[4];
    const float* enc       = (const float*)d_in[5];
    const float* emb_tok   = (const float*)d_in[6];
    const float* emb_pos   = (const float*)d_in[7];
    const float* emb_year  = (const float*)d_in[8];
    const float* emb_inst  = (const float*)d_in[9];
    const float* W_ih      = (const float*)d_in[10];
    const float* b_ih      = (const float*)d_in[11];
    const float* W_hh      = (const float*)d_in[12];
    const float* b_hh      = (const float*)d_in[13];
    const float* W_concat  = (const float*)d_in[14];
    const float* b_concat  = (const float*)d_in[15];
    const float* W_out     = (const float*)d_in[16];
    const float* b_out     = (const float*)d_in[17];

    float* out = (float*)d_out;
    float* out_logits = out;
    float* out_h = nullptr;
    float* out_attn = nullptr;
    long long need = (long long)Bq * Vq + (long long)Bq * Hq + (long long)Bq * Sq;
    if ((long long)out_size >= need) {
        out_h = out + (size_t)Bq * Vq;
        out_attn = out_h + (size_t)Bq * Hq;
    }

    float* concat_out;
    cudaGetSymbolAddress((void**)&concat_out, g_concat_out);

    cudaFuncSetAttribute(gemm_gru, cudaFuncAttributeMaxDynamicSharedMemorySize, GEMM_SMEM_BYTES);
    cudaFuncSetAttribute(gemm_concat, cudaFuncAttributeMaxDynamicSharedMemorySize, GEMM_SMEM_BYTES);
    cudaFuncSetAttribute(gemm_vocab, cudaFuncAttributeMaxDynamicSharedMemorySize, VOC_SMEM_BYTES);

    // 1. gx+gh GEMMs (embedding gather fused) + grid barrier + GRU gates
    gemm_gru<<<dim3(12, 8, 2), 256, GEMM_SMEM_BYTES>>>(last_h, W_ih, W_hh,
        input_seq, positions, years, froms, emb_tok, emb_pos, emb_year, emb_inst,
        b_ih, b_hh, out_h);
    // 2. fused scores + online-softmax context (single pass, one resident wave)
    attn_fused_kernel<<<dim3(8, Bq), 128>>>(enc);
    // 3. merged epilogue: stats inline + ctx reduce + attn weights
    attn_epilogue_kernel<<<dim3(18, Bq), 256>>>(out_attn);
    // 4. concat GEMM + grid barrier + reduce + tanh (pre-rounds A to tf32)
    gemm_concat<<<dim3(4, 16), 256, GEMM_SMEM_BYTES>>>(W_concat, b_concat);
    // 5. vocab logits: k32-staged tf32 GEMM, cvt-free A path, direct to out
    gemm_vocab<<<Vq / 128, 256, VOC_SMEM_BYTES>>>(concat_out, W_out, b_out, out_logits);
}

// round 17
// speedup vs baseline: 1.0186x; 1.0186x over previous
#include <cuda_runtime.h>
#include <cuda_bf16.h>
#include <math.h>
#include <stdint.h>

#define Bq 128
#define Sq 4096
#define Hq 512
#define Vq 32000
#define NCHUNK 32           // 32 chunks of 128 s each

// ---------------- scratch (no allocations allowed) ----------------
__device__ float g_hnew[Bq * Hq];
__device__ float g_scores[Bq * Sq];
__device__ float g_pm[Bq * NCHUNK];
__device__ float g_pz[Bq * NCHUNK];
__device__ float g_pctx[Bq * NCHUNK * Hq];
__device__ float g_concat_in[Bq * 2 * Hq];
__device__ float g_concat_out[Bq * Hq];
__device__ float g_gemm_part [8 * Bq * 3 * Hq];
__device__ float g_gemm_part2[8 * Bq * 3 * Hq];
__device__ int   g_cnt1 = 0, g_fin1 = 0;   // gemm_gru grid barrier
__device__ int   g_cnt2 = 0, g_fin2 = 0;   // concat gemm grid barrier

// ---------------- grid barrier helpers (all blocks co-resident) ----------------
__device__ __forceinline__ void grid_arrive_wait(int* cnt, int nblocks)
{
    __syncthreads();
    __threadfence();
    if (threadIdx.x == 0) {
        atomicAdd(cnt, 1);
        while (*((volatile int*)cnt) < nblocks) __nanosleep(64);
    }
    __syncthreads();
    __threadfence();
}
__device__ __forceinline__ void grid_finish_reset(int* cnt, int* fin, int nblocks)
{
    __syncthreads();
    if (threadIdx.x == 0) {
        int d = atomicAdd(fin, 1);
        if (d == nblocks - 1) { *cnt = 0; *fin = 0; }
    }
}

// ---------------- tf32 helpers ----------------
__device__ __forceinline__ uint32_t f2tf32(float x) {
    uint32_t r;
    asm("cvt.rna.tf32.f32 %0, %1;" : "=r"(r) : "f"(x));
    return r;
}
__device__ __forceinline__ float tf32f(float x) { return __uint_as_float(f2tf32(x)); }
__device__ __forceinline__ void mma_tf32(float* d, const uint32_t* a, const uint32_t* b) {
    asm("mma.sync.aligned.m16n8k8.row.col.f32.tf32.tf32.f32 "
        "{%0,%1,%2,%3}, {%4,%5,%6,%7}, {%8,%9}, {%0,%1,%2,%3};"
        : "+f"(d[0]), "+f"(d[1]), "+f"(d[2]), "+f"(d[3])
        : "r"(a[0]), "r"(a[1]), "r"(a[2]), "r"(a[3]), "r"(b[0]), "r"(b[1]));
}
__device__ __forceinline__ void cp16(void* dst_smem, const void* src) {
    uint32_t d = (uint32_t)__cvta_generic_to_shared(dst_smem);
    asm volatile("cp.async.ca.shared.global [%0], [%1], 16;" :: "r"(d), "l"(src));
}
__device__ __forceinline__ void cp_commit() { asm volatile("cp.async.commit_group;"); }
template<int N> __device__ __forceinline__ void cp_wait() {
    asm volatile("cp.async.wait_group %0;" :: "n"(N));
}

#define LDA 20
#define TILE_F (128 * LDA)
#define GEMM_SMEM_BYTES (3 * 2 * TILE_F * 4)

// vocab: k32 stages, padded stride 36 -> (36r+c)%32 = 4r+c, conflict-free frags
#define VLDA 36
#define VTILE_F (128 * VLDA)
#define VOC_SMEM_BYTES (3 * 2 * VTILE_F * 4)   // 110592 B -> 2 CTAs/SM (221 KB)

// ---------------- generic tf32x3 body (gru/concat), 3-deep cp.async ring ----------------
__device__ __forceinline__
void gemm_body(const float* aptr0, const float* aptr1,
               const float* wptr0, const float* wptr1,
               float* __restrict__ part, int N,
               int nblk, int nsteps)
{
    extern __shared__ float smx[];
    float* Asm = smx;
    float* Wsm = smx + 3 * TILE_F;

    int t = threadIdx.x;
    int wid = t >> 5, lane = t & 31;
    int lr = lane >> 2, lc = lane & 3;
    int m0 = (wid & 3) * 32;
    int n0 = (wid >> 2) * 64;
    int r0 = t >> 2;
    int k4 = (t & 3) * 4;

    float acc[2][8][4];
#pragma unroll
    for (int i = 0; i < 2; i++)
#pragma unroll
        for (int j = 0; j < 8; j++)
#pragma unroll
            for (int c = 0; c < 4; c++) acc[i][j][c] = 0.f;

#define STAGE(buf, step)                                              \
    do {                                                              \
        float* Ad = Asm + (buf) * TILE_F;                             \
        float* Wd = Wsm + (buf) * TILE_F;                             \
        cp16(Ad + r0 * LDA + k4,        aptr0 + (step) * 16);         \
        cp16(Ad + (r0 + 64) * LDA + k4, aptr1 + (step) * 16);         \
        cp16(Wd + r0 * LDA + k4,        wptr0 + (step) * 16);         \
        cp16(Wd + (r0 + 64) * LDA + k4, wptr1 + (step) * 16);         \
        cp_commit();                                                  \
    } while (0)

#pragma unroll
    for (int p = 0; p < 3; p++) {
        if (p < nsteps) STAGE(p, p);
        else cp_commit();
    }

    for (int i = 0; i < nsteps; i++) {
        cp_wait<2>();
        __syncthreads();
        int buf = i % 3;
        const float* Ab = Asm + buf * TILE_F;
        const float* Wb = Wsm + buf * TILE_F;
#pragma unroll
        for (int ks = 0; ks < 2; ks++) {
            int k0 = ks * 8;
            uint32_t ah[2][4], al[2][4];
#pragma unroll
            for (int tt = 0; tt < 2; tt++) {
                int rb = m0 + tt * 16;
#pragma unroll
                for (int q = 0; q < 4; q++) {
                    int rr = rb + lr + (q & 1) * 8;
                    int cc = k0 + lc + (q >> 1) * 4;
                    float x = Ab[rr * LDA + cc];
                    uint32_t hi = f2tf32(x);
                    ah[tt][q] = hi;
                    al[tt][q] = f2tf32(x - __uint_as_float(hi));
                }
            }
#pragma unroll
            for (int j = 0; j < 8; j++) {
                int rn = (n0 + j * 8 + lr) * LDA;
                float x0 = Wb[rn + k0 + lc];
                float x1 = Wb[rn + k0 + lc + 4];
                uint32_t bh[2], bl[2];
                bh[0] = f2tf32(x0); bl[0] = f2tf32(x0 - __uint_as_float(bh[0]));
                bh[1] = f2tf32(x1); bl[1] = f2tf32(x1 - __uint_as_float(bh[1]));
#pragma unroll
                for (int tt = 0; tt < 2; tt++) {
                    mma_tf32(acc[tt][j], ah[tt], bh);
                    mma_tf32(acc[tt][j], ah[tt], bl);
                    mma_tf32(acc[tt][j], al[tt], bh);
                }
            }
        }
        __syncthreads();
        int nx = i + 3;
        if (nx < nsteps) STAGE(buf, nx);
        else cp_commit();
    }
#undef STAGE

#pragma unroll
    for (int tt = 0; tt < 2; tt++)
#pragma unroll
        for (int j = 0; j < 8; j++) {
            int gr = m0 + tt * 16 + lr;
            int gc = nblk + n0 + j * 8 + 2 * lc;
            *(float2*)(part + (size_t)gr * N + gc) = make_float2(acc[tt][j][0], acc[tt][j][1]);
            *(float2*)(part + (size_t)(gr + 8) * N + gc) = make_float2(acc[tt][j][2], acc[tt][j][3]);
        }
}

// ---------------- vocab GEMM v4: 512 threads, 16 warps, 32x32 warp tiles ----------------
// C[128,Vq] = A[128,512] @ W[Vq,512]^T + bias. grid 250, block 512, 2 CTAs/SM
// -> 32 warps/SM. A is tf32-prerounded (plain LDS); W cvt at fragment load.
__global__ __launch_bounds__(512, 2)
void gemm_vocab(const float* __restrict__ A,
                const float* __restrict__ W,
                const float* __restrict__ bias,
                float* __restrict__ C)
{
    extern __shared__ float smx[];
    float* Asm = smx;
    float* Wsm = smx + 3 * VTILE_F;

    const int K = Hq;
    const int N = Vq;
    int t = threadIdx.x;
    int wid = t >> 5, lane = t & 31;
    int lr = lane >> 2, lc = lane & 3;
    int m0 = (wid & 3) * 32;        // 4 m-groups
    int n0 = (wid >> 2) * 32;       // 4 n-groups
    int nblk = blockIdx.x * 128;
    int row = t >> 2;               // 0..127 (4 threads per row)
    int kc8 = (t & 3) * 8;          // 8-float segment within 32-float chunk

    const float* aptr = A + (size_t)row * K + kc8;
    const float* wptr = W + (size_t)(nblk + row) * K + kc8;

    float acc[2][4][4];
#pragma unroll
    for (int i = 0; i < 2; i++)
#pragma unroll
        for (int j = 0; j < 4; j++)
#pragma unroll
            for (int c = 0; c < 4; c++) acc[i][j][c] = 0.f;

    const int nsteps = K / 32;      // 16

#define VSTG(buf, step)                                               \
    do {                                                              \
        float* Ad = Asm + (buf) * VTILE_F + row * VLDA + kc8;         \
        float* Wd = Wsm + (buf) * VTILE_F + row * VLDA + kc8;         \
        const float* as = aptr + (step) * 32;                         \
        const float* ws = wptr + (step) * 32;                         \
        cp16(Ad,     as);  cp16(Ad + 4, as + 4);                      \
        cp16(Wd,     ws);  cp16(Wd + 4, ws + 4);                      \
        cp_commit();                                                  \
    } while (0)

    VSTG(0, 0); VSTG(1, 1); VSTG(2, 2);

    for (int i = 0; i < nsteps; i++) {
        cp_wait<2>();
        __syncthreads();
        int buf = i % 3;
        const float* Ab = Asm + buf * VTILE_F;
        const float* Wb = Wsm + buf * VTILE_F;
#pragma unroll
        for (int ks = 0; ks < 4; ks++) {
            int k0 = ks * 8;
            uint32_t ah[2][4];
#pragma unroll
            for (int tt = 0; tt < 2; tt++) {
                int rb = m0 + tt * 16;
                ah[tt][0] = __float_as_uint(Ab[(rb + lr) * VLDA + k0 + lc]);
                ah[tt][1] = __float_as_uint(Ab[(rb + lr + 8) * VLDA + k0 + lc]);
                ah[tt][2] = __float_as_uint(Ab[(rb + lr) * VLDA + k0 + lc + 4]);
                ah[tt][3] = __float_as_uint(Ab[(rb + lr + 8) * VLDA + k0 + lc + 4]);
            }
#pragma unroll
            for (int j = 0; j < 4; j++) {
                int rn = (n0 + j * 8 + lr) * VLDA;
                uint32_t bh[2];
                bh[0] = f2tf32(Wb[rn + k0 + lc]);
                bh[1] = f2tf32(Wb[rn + k0 + lc + 4]);
                mma_tf32(acc[0][j], ah[0], bh);
                mma_tf32(acc[1][j], ah[1], bh);
            }
        }
        __syncthreads();
        int nx = i + 3;
        if (nx < nsteps) VSTG(buf, nx);
        else cp_commit();
    }
#undef VSTG

#pragma unroll
    for (int tt = 0; tt < 2; tt++)
#pragma unroll
        for (int j = 0; j < 4; j++) {
            int gr = m0 + tt * 16 + lr;
            int gc = nblk + n0 + j * 8 + 2 * lc;
            float b0 = bias[gc], b1 = bias[gc + 1];
            *(float2*)(C + (size_t)gr * N + gc) = make_float2(acc[tt][j][0] + b0, acc[tt][j][1] + b1);
            *(float2*)(C + (size_t)(gr + 8) * N + gc) = make_float2(acc[tt][j][2] + b0, acc[tt][j][3] + b1);
        }
}

// fused GRU GEMMs + embedding gather + grid-barrier + gate epilogue
#define GRU_NB 192
__global__ __launch_bounds__(256, 2)
void gemm_gru(const float* __restrict__ hprev,
              const float* __restrict__ W_ih, const float* __restrict__ W_hh,
              const int* __restrict__ seq, const int* __restrict__ pos,
              const int* __restrict__ yr, const int* __restrict__ fr,
              const float* __restrict__ et, const float* __restrict__ ep,
              const float* __restrict__ ey, const float* __restrict__ ei,
              const float* __restrict__ b_ih, const float* __restrict__ b_hh,
              float* __restrict__ out_h)
{
    int N = 3 * Hq;
    int nblk = blockIdx.x * 128;
    int t = threadIdx.x;
    int r0 = t >> 2;
    int k4 = (t & 3) * 4;
    if (blockIdx.z == 0) {
        int K = 4 * Hq;
        int klen = K / 8;               // 256 -> one table per split
        int kstart = blockIdx.y * klen;
        int region = blockIdx.y >> 1;
        int coff = (blockIdx.y & 1) * 256 + k4;
        const float* tbl; const int* idxa;
        if (region == 0)      { tbl = et; idxa = seq; }
        else if (region == 1) { tbl = ep; idxa = pos; }
        else if (region == 2) { tbl = ey; idxa = yr; }
        else                  { tbl = ei; idxa = fr; }
        const float* a0 = tbl + (size_t)idxa[r0] * Hq + coff;
        const float* a1 = tbl + (size_t)idxa[r0 + 64] * Hq + coff;
        gemm_body(a0, a1,
                  W_ih + (size_t)(nblk + r0) * K + kstart + k4,
                  W_ih + (size_t)(nblk + r0 + 64) * K + kstart + k4,
                  g_gemm_part + (size_t)blockIdx.y * 128 * N, N,
                  nblk, klen / 16);
    } else {
        int K = Hq;
        int klen = K / 8;
        int kstart = blockIdx.y * klen;
        gemm_body(hprev + (size_t)r0 * K + kstart + k4,
                  hprev + (size_t)(r0 + 64) * K + kstart + k4,
                  W_hh + (size_t)(nblk + r0) * K + kstart + k4,
                  W_hh + (size_t)(nblk + r0 + 64) * K + kstart + k4,
                  g_gemm_part2 + (size_t)blockIdx.y * 128 * N, N,
                  nblk, klen / 16);
    }

    grid_arrive_wait(&g_cnt1, GRU_NB);

    int lb = (blockIdx.z * 8 + blockIdx.y) * 12 + blockIdx.x;
    for (int idx = lb * 256 + t; idx < Bq * Hq; idx += GRU_NB * 256) {
        int b = idx >> 9;
        int j = idx & 511;
        float xr = 0.f, xz = 0.f, xn = 0.f, hr = 0.f, hz = 0.f, hn = 0.f;
#pragma unroll
        for (int z = 0; z < 8; z++) {
            const float* P0 = g_gemm_part  + ((size_t)z * Bq + b) * (3 * Hq);
            const float* P1 = g_gemm_part2 + ((size_t)z * Bq + b) * (3 * Hq);
            xr += P0[j]; xz += P0[Hq + j]; xn += P0[2 * Hq + j];
            hr += P1[j]; hz += P1[Hq + j]; hn += P1[2 * Hq + j];
        }
        xr += b_ih[j]; xz += b_ih[Hq + j]; xn += b_ih[2 * Hq + j];
        hr += b_hh[j]; hz += b_hh[Hq + j]; hn += b_hh[2 * Hq + j];
        float r = 1.f / (1.f + __expf(-(xr + hr)));
        float z = 1.f / (1.f + __expf(-(xz + hz)));
        float n = tanhf(xn + r * hn);
        float hnew = (1.f - z) * n + z * hprev[idx];
        g_hnew[idx] = hnew;
        g_concat_in[(size_t)b * 2 * Hq + j] = hnew;
        if (out_h) out_h[idx] = hnew;
    }

    grid_finish_reset(&g_cnt1, &g_fin1, GRU_NB);
}

// concat GEMM + grid-barrier + split-K reduce + tanh epilogue
#define CC_NB 64
__global__ __launch_bounds__(256, 2)
void gemm_concat(const float* __restrict__ W_concat,
                 const float* __restrict__ b_concat)
{
    int N = Hq;
    int K = 2 * Hq;
    int klen = K / 16;                  // 64 -> nsteps 4
    int kstart = blockIdx.y * klen;
    int nblk = blockIdx.x * 128;
    int t = threadIdx.x;
    int r0 = t >> 2;
    int k4 = (t & 3) * 4;
    const float* A = g_concat_in;
    gemm_body(A + (size_t)r0 * K + kstart + k4,
              A + (size_t)(r0 + 64) * K + kstart + k4,
              W_concat + (size_t)(nblk + r0) * K + kstart + k4,
              W_concat + (size_t)(nblk + r0 + 64) * K + kstart + k4,
              g_gemm_part + (size_t)blockIdx.y * 128 * N, N,
              nblk, klen / 16);

    grid_arrive_wait(&g_cnt2, CC_NB);

    int lb = blockIdx.y * 4 + blockIdx.x;
    for (int idx = lb * 256 + t; idx < Bq * Hq; idx += CC_NB * 256) {
        float s = 0.f;
#pragma unroll
        for (int z = 0; z < 16; z++)
            s += g_gemm_part[(size_t)z * Bq * Hq + idx];
        s += b_concat[idx & 511];
        // pre-round to tf32: bit-identical to rounding at vocab fragment load
        g_concat_out[idx] = tf32f(tanhf(s));
    }

    grid_finish_reset(&g_cnt2, &g_fin2, CC_NB);
}

// ---------------- fused attention: single pass over enc ----------------
__global__ __launch_bounds__(128)
void attn_fused_kernel(const float* __restrict__ enc)
{
    int b = blockIdx.y;
    int t = threadIdx.x;
    int w = t >> 5;
    int lane = t & 31;
    int chunk = blockIdx.x * 4 + w;

    const float4* h4 = (const float4*)(g_hnew + (size_t)b * Hq);
    float4 h0 = h4[lane];
    float4 h1 = h4[lane + 32];
    float4 h2 = h4[lane + 64];
    float4 h3 = h4[lane + 96];

    float m = -1e30f, Z = 0.f;
    float4 c0 = make_float4(0.f,0.f,0.f,0.f), c1 = c0, c2 = c0, c3 = c0;

    int sbase = chunk * 128;
#pragma unroll 2
    for (int s0 = 0; s0 < 128; s0++) {
        int s = sbase + s0;
        const float4* e4 = (const float4*)(enc + ((size_t)s * Bq + b) * Hq);
        float4 e0 = e4[lane];
        float4 e1 = e4[lane + 32];
        float4 e2 = e4[lane + 64];
        float4 e3 = e4[lane + 96];
        float dp = e0.x*h0.x + e0.y*h0.y + e0.z*h0.z + e0.w*h0.w
                 + e1.x*h1.x + e1.y*h1.y + e1.z*h1.z + e1.w*h1.w
                 + e2.x*h2.x + e2.y*h2.y + e2.z*h2.z + e2.w*h2.w
                 + e3.x*h3.x + e3.y*h3.y + e3.z*h3.z + e3.w*h3.w;
#pragma unroll
        for (int off = 16; off > 0; off >>= 1)
            dp += __shfl_xor_sync(0xffffffffu, dp, off);
        if (lane == 0) g_scores[(size_t)b * Sq + s] = dp;
        if (dp <= m) {
            float p = __expf(dp - m);
            Z += p;
            c0.x += p*e0.x; c0.y += p*e0.y; c0.z += p*e0.z; c0.w += p*e0.w;
            c1.x += p*e1.x; c1.y += p*e1.y; c1.z += p*e1.z; c1.w += p*e1.w;
            c2.x += p*e2.x; c2.y += p*e2.y; c2.z += p*e2.z; c2.w += p*e2.w;
            c3.x += p*e3.x; c3.y += p*e3.y; c3.z += p*e3.z; c3.w += p*e3.w;
        } else {
            float corr = __expf(m - dp);
            Z = Z * corr + 1.f;
            c0.x = c0.x*corr + e0.x; c0.y = c0.y*corr + e0.y; c0.z = c0.z*corr + e0.z; c0.w = c0.w*corr + e0.w;
            c1.x = c1.x*corr + e1.x; c1.y = c1.y*corr + e1.y; c1.z = c1.z*corr + e1.z; c1.w = c1.w*corr + e1.w;
            c2.x = c2.x*corr + e2.x; c2.y = c2.y*corr + e2.y; c2.z = c2.z*corr + e2.z; c2.w = c2.w*corr + e2.w;
            c3.x = c3.x*corr + e3.x; c3.y = c3.y*corr + e3.y; c3.z = c3.z*corr + e3.z; c3.w = c3.w*corr + e3.w;
            m = dp;
        }
    }

    int pc = b * NCHUNK + chunk;
    float4* pctx = (float4*)(g_pctx + (size_t)pc * Hq);
    pctx[lane]      = c0;
    pctx[lane + 32] = c1;
    pctx[lane + 64] = c2;
    pctx[lane + 96] = c3;
    if (lane == 0) { g_pm[pc] = m; g_pz[pc] = Z; }
}

// ---------------- merged attention epilogue ----------------
__global__ __launch_bounds__(256)
void attn_epilogue_kernel(float* __restrict__ out_attn)
{
    __shared__ float s_scale[NCHUNK];
    __shared__ float s_M, s_Zinv;
    int b = blockIdx.y;
    int part = blockIdx.x;
    int t = threadIdx.x;

    if (t < 32) {
        float m = g_pm[b * NCHUNK + t];
        float z = g_pz[b * NCHUNK + t];
        float M = m;
#pragma unroll
        for (int off = 16; off > 0; off >>= 1)
            M = fmaxf(M, __shfl_xor_sync(0xffffffffu, M, off));
        float e = __expf(m - M);
        float zs = z * e;
#pragma unroll
        for (int off = 16; off > 0; off >>= 1)
            zs += __shfl_xor_sync(0xffffffffu, zs, off);
        float zinv = 1.f / zs;
        s_scale[t] = e * zinv;
        if (t == 0) { s_M = M; s_Zinv = zinv; }
    }
    __syncthreads();

    if (part < 2) {
        int h = part * 256 + t;
        const float* p = g_pctx + (size_t)b * NCHUNK * Hq + h;
        float a = 0.f;
#pragma unroll 8
        for (int c = 0; c < NCHUNK; c++)
            a += p[(size_t)c * Hq] * s_scale[c];
        g_concat_in[(size_t)b * 2 * Hq + Hq + h] = a;
    } else if (out_attn) {
        int s = (part - 2) * 256 + t;
        out_attn[(size_t)b * Sq + s] =
            __expf(g_scores[(size_t)b * Sq + s] - s_M) * s_Zinv;
    }
}

// ---------------- launch ----------------
extern "C" void kernel_launch(void* const* d_in, const int* in_sizes, int n_in,
                              void* d_out, int out_size)
{
    const int* input_seq   = (const int*)d_in[0];
    const int* positions   = (const int*)d_in[1];
    const int* years       = (const int*)d_in[2];
    const int* froms       = (const int*)d_in[3];
    const float* last_h    = (const float*)d_in[4];
    const float* enc       = (const float*)d_in[5];
    const float* emb_tok   = (const float*)d_in[6];
    const float* emb_pos   = (const float*)d_in[7];
    const float* emb_year  = (const float*)d_in[8];
    const float* emb_inst  = (const float*)d_in[9];
    const float* W_ih      = (const float*)d_in[10];
    const float* b_ih      = (const float*)d_in[11];
    const float* W_hh      = (const float*)d_in[12];
    const float* b_hh      = (const float*)d_in[13];
    const float* W_concat  = (const float*)d_in[14];
    const float* b_concat  = (const float*)d_in[15];
    const float* W_out     = (const float*)d_in[16];
    const float* b_out     = (const float*)d_in[17];

    float* out = (float*)d_out;
    float* out_logits = out;
    float* out_h = nullptr;
    float* out_attn = nullptr;
    long long need = (long long)Bq * Vq + (long long)Bq * Hq + (long long)Bq * Sq;
    if ((long long)out_size >= need) {
        out_h = out + (size_t)Bq * Vq;
        out_attn = out_h + (size_t)Bq * Hq;
    }

    float* concat_out;
    cudaGetSymbolAddress((void**)&concat_out, g_concat_out);

    cudaFuncSetAttribute(gemm_gru, cudaFuncAttributeMaxDynamicSharedMemorySize, GEMM_SMEM_BYTES);
    cudaFuncSetAttribute(gemm_concat, cudaFuncAttributeMaxDynamicSharedMemorySize, GEMM_SMEM_BYTES);
    cudaFuncSetAttribute(gemm_vocab, cudaFuncAttributeMaxDynamicSharedMemorySize, VOC_SMEM_BYTES);

    // 1. gx+gh GEMMs (embedding gather fused) + grid barrier + GRU gates
    gemm_gru<<<dim3(12, 8, 2), 256, GEMM_SMEM_BYTES>>>(last_h, W_ih, W_hh,
        input_seq, positions, years, froms, emb_tok, emb_pos, emb_year, emb_inst,
        b_ih, b_hh, out_h);
    // 2. fused scores + online-softmax context (single pass, one resident wave)
    attn_fused_kernel<<<dim3(8, Bq), 128>>>(enc);
    // 3. merged epilogue: stats inline + ctx reduce + attn weights
    attn_epilogue_kernel<<<dim3(18, Bq), 256>>>(out_attn);
    // 4. concat GEMM + grid barrier + reduce + tanh (pre-rounds A to tf32)
    gemm_concat<<<dim3(4, 16), 256, GEMM_SMEM_BYTES>>>(W_concat, b_concat);
    // 5. vocab logits: 512-thread blocks, 32 warps/SM, single wave
    gemm_vocab<<<Vq / 128, 512, VOC_SMEM_BYTES>>>(concat_out, W_out, b_out, out_logits);
}